// round 11
// baseline (speedup 1.0000x reference)
#include <cuda_runtime.h>
#include <cuda_fp16.h>

#define N0V   8192
#define N1V   100000
#define N2V   300000
#define KNBR  32
#define DD    64

typedef unsigned long long u64t;

#define PACKU64(out, lo, hi)  asm("mov.b64 %0, {%1, %2};" : "=l"(out) : "f"(lo), "f"(hi))
#define SPLATF64(out, v)      asm("mov.b64 %0, {%1, %1};" : "=l"(out) : "f"(v))
#define UNPACKF64(lo, hi, in) asm("mov.b64 {%0, %1}, %2;" : "=f"(lo), "=f"(hi) : "l"(in))
#define FFMA2(acc, a, b)      asm("fma.rn.f32x2 %0, %1, %2, %0;" : "+l"(acc) : "l"(a), "l"(b))

// Scratch (device globals — allocation in kernel_launch is forbidden).
__device__ __half g_v2h[(size_t)N2V * DD];    // 38.4 MB gather target
__device__ __half g_agg1[(size_t)N1V * DD];   // 12.8 MB hop-1 aggregates
__device__ __half g_h1h[(size_t)N1V * DD];    // 12.8 MB hop-1 activations
__device__ __half g_agg0[(size_t)N0V * DD];   // 1 MB   seed aggregates

// ---------------------------------------------------------------------------
// K1: v2h = half(feats[node_ids2]); 2 rows per thread for MLP.
// ---------------------------------------------------------------------------
__global__ void gather_v2h_kernel(const float* __restrict__ feats,
                                  const int*   __restrict__ node_ids2)
{
    int t = blockIdx.x * blockDim.x + threadIdx.x;
    const int half_total = (N2V / 2) * (DD / 4);
    if (t >= half_total) return;
    int row  = t >> 4;
    int c    = t & 15;
    int row2 = row + N2V / 2;
    int s1 = __ldg(node_ids2 + row);
    int s2 = __ldg(node_ids2 + row2);
    float4 v1 = __ldg((const float4*)(feats + (size_t)s1 * DD) + c);
    float4 v2 = __ldg((const float4*)(feats + (size_t)s2 * DD) + c);

    __half2 a0 = __floats2half2_rn(v1.x, v1.y);
    __half2 a1 = __floats2half2_rn(v1.z, v1.w);
    __half2 b0 = __floats2half2_rn(v2.x, v2.y);
    __half2 b1 = __floats2half2_rn(v2.z, v2.w);
    uint2 p1, p2;
    p1.x = *(unsigned int*)&a0;  p1.y = *(unsigned int*)&a1;
    p2.x = *(unsigned int*)&b0;  p2.y = *(unsigned int*)&b1;
    ((uint2*)g_v2h)[(size_t)row  * 16 + c] = p1;
    ((uint2*)g_v2h)[(size_t)row2 * 16 + c] = p2;
}

// ---------------------------------------------------------------------------
// Wide-load gather-mean (validated). Warp handles 2 rows; LDG.128 fetches
// 4 whole neighbor rows per instruction.
// ---------------------------------------------------------------------------
__global__ void __launch_bounds__(256) agg_mean_kernel(
    const uint4* __restrict__ vsrc,    // [nsrc] rows of 8 x uint4 (128B)
    const int*   __restrict__ nbr,     // [nrows][KNBR]
    __half*      __restrict__ aggout,  // [nrows][DD] fp16
    int nrows)
{
    const int tid  = threadIdx.x;
    const int lane = tid & 31;
    const int warp = tid >> 5;
    const int rowA = blockIdx.x * 16 + warp * 2;
    const int rowB = rowA + 1;
    const int crA = min(rowA, nrows - 1);
    const int crB = min(rowB, nrows - 1);

    const int idxA = __ldg(nbr + (size_t)crA * KNBR + lane);
    const int idxB = __ldg(nbr + (size_t)crB * KNBR + lane);

    const int sub = lane >> 3;
    const int ch  = lane & 7;

    __half2 zero = __float2half2_rn(0.f);
    __half2 aAcc[2][4], bAcc[2][4];
    #pragma unroll
    for (int s = 0; s < 2; ++s)
        #pragma unroll
        for (int j = 0; j < 4; ++j) { aAcc[s][j] = zero; bAcc[s][j] = zero; }

    #pragma unroll
    for (int i = 0; i < 8; ++i) {
        int nA = __shfl_sync(0xffffffffu, idxA, 4 * i + sub);
        int nB = __shfl_sync(0xffffffffu, idxB, 4 * i + sub);
        uint4 dA = __ldg(vsrc + (size_t)nA * 8 + ch);
        uint4 dB = __ldg(vsrc + (size_t)nB * 8 + ch);
        const __half2* hA = (const __half2*)&dA;
        const __half2* hB = (const __half2*)&dB;
        int s = i & 1;
        #pragma unroll
        for (int j = 0; j < 4; ++j) {
            aAcc[s][j] = __hadd2(aAcc[s][j], hA[j]);
            bAcc[s][j] = __hadd2(bAcc[s][j], hB[j]);
        }
    }

    float fA[8], fB[8];
    #pragma unroll
    for (int j = 0; j < 4; ++j) {
        float2 va = __half22float2(__hadd2(aAcc[0][j], aAcc[1][j]));
        float2 vb = __half22float2(__hadd2(bAcc[0][j], bAcc[1][j]));
        fA[2 * j] = va.x;  fA[2 * j + 1] = va.y;
        fB[2 * j] = vb.x;  fB[2 * j + 1] = vb.y;
    }

    #pragma unroll
    for (int d = 8; d <= 16; d <<= 1) {
        #pragma unroll
        for (int j = 0; j < 8; ++j) {
            fA[j] += __shfl_xor_sync(0xffffffffu, fA[j], d);
            fB[j] += __shfl_xor_sync(0xffffffffu, fB[j], d);
        }
    }

    const float inv = 1.0f / KNBR;
    if (sub == 0 && rowA < nrows) {
        __half2 h[4];
        #pragma unroll
        for (int j = 0; j < 4; ++j)
            h[j] = __floats2half2_rn(fA[2 * j] * inv, fA[2 * j + 1] * inv);
        ((uint4*)aggout)[(size_t)rowA * 8 + ch] = *(uint4*)h;
    }
    if (sub == 1 && rowB < nrows) {
        __half2 h[4];
        #pragma unroll
        for (int j = 0; j < 4; ++j)
            h[j] = __floats2half2_rn(fB[2 * j] * inv, fB[2 * j + 1] * inv);
        ((uint4*)aggout)[(size_t)rowB * 8 + ch] = *(uint4*)h;
    }
}

// ---------------------------------------------------------------------------
// FFMA GEMM (validated R7): out = relu(A @ W + b), A fp16 [nrows,64].
// 128 rows per block of 256 threads; thread = 4 rows x 8 cols, f32x2 FMA.
// Templated output type: fp16 (hop-1) or fp32 (seed).
// ---------------------------------------------------------------------------
template<bool HALF_OUT>
__global__ void __launch_bounds__(256) gemm64_kernel(
    const __half* __restrict__ A,
    const float*  __restrict__ W,
    const float*  __restrict__ bias,
    void*         __restrict__ out,
    int nrows)
{
    __shared__ float  sW[DD * DD];
    __shared__ __half sA[128 * 72];

    const int tid = threadIdx.x;
    #pragma unroll
    for (int i = tid; i < DD * DD / 4; i += 256)
        ((float4*)sW)[i] = __ldg((const float4*)W + i);

    const int rowbase = blockIdx.x * 128;
    for (int i = tid; i < 1024; i += 256) {
        int r = i >> 3, c = i & 7;
        int gr = min(rowbase + r, nrows - 1);
        uint4 v = __ldg((const uint4*)(A + (size_t)gr * DD) + c);
        *(uint4*)&sA[r * 72 + c * 8] = v;
    }
    __syncthreads();

    const int rp   = tid >> 3;
    const int col0 = (tid & 7) * 8;

    float4 bv0 = __ldg((const float4*)(bias + col0));
    float4 bv1 = __ldg((const float4*)(bias + col0 + 4));
    u64t bp[4];
    PACKU64(bp[0], bv0.x, bv0.y);  PACKU64(bp[1], bv0.z, bv0.w);
    PACKU64(bp[2], bv1.x, bv1.y);  PACKU64(bp[3], bv1.z, bv1.w);
    u64t acc[4][4];
    #pragma unroll
    for (int r = 0; r < 4; ++r)
        #pragma unroll
        for (int j = 0; j < 4; ++j) acc[r][j] = bp[j];

    #pragma unroll
    for (int k = 0; k < DD; k += 2) {
        ulonglong2 wA01 = *(const ulonglong2*)&sW[k * DD + col0];
        ulonglong2 wA23 = *(const ulonglong2*)&sW[k * DD + col0 + 4];
        ulonglong2 wB01 = *(const ulonglong2*)&sW[(k + 1) * DD + col0];
        ulonglong2 wB23 = *(const ulonglong2*)&sW[(k + 1) * DD + col0 + 4];
        #pragma unroll
        for (int r = 0; r < 4; ++r) {
            __half2 ah = *(const __half2*)&sA[(4 * rp + r) * 72 + k];
            float2 af = __half22float2(ah);
            u64t s0, s1;
            SPLATF64(s0, af.x);
            SPLATF64(s1, af.y);
            FFMA2(acc[r][0], s0, wA01.x);  FFMA2(acc[r][1], s0, wA01.y);
            FFMA2(acc[r][2], s0, wA23.x);  FFMA2(acc[r][3], s0, wA23.y);
            FFMA2(acc[r][0], s1, wB01.x);  FFMA2(acc[r][1], s1, wB01.y);
            FFMA2(acc[r][2], s1, wB23.x);  FFMA2(acc[r][3], s1, wB23.y);
        }
    }

    #pragma unroll
    for (int r = 0; r < 4; ++r) {
        int grow = rowbase + 4 * rp + r;
        if (grow >= nrows) continue;
        if (HALF_OUT) {
            __half2 h[4];
            #pragma unroll
            for (int j = 0; j < 4; ++j) {
                float lo, hi;
                UNPACKF64(lo, hi, acc[r][j]);
                h[j] = __floats2half2_rn(fmaxf(lo, 0.f), fmaxf(hi, 0.f));
            }
            *(uint4*)((__half*)out + (size_t)grow * DD + col0) = *(uint4*)h;
        } else {
            float* op = (float*)out + (size_t)grow * DD + col0;
            #pragma unroll
            for (int j = 0; j < 4; ++j) {
                float lo, hi;
                UNPACKF64(lo, hi, acc[r][j]);
                op[2 * j]     = fmaxf(lo, 0.f);
                op[2 * j + 1] = fmaxf(hi, 0.f);
            }
        }
    }
}

// ---------------------------------------------------------------------------
// Inputs: 0 feats, 1 W0, 2 b0, 3 W1, 4 b1, 5 neigh_idx0, 6 neigh_idx1,
//         7 node_ids1 (unused), 8 node_ids2
// ---------------------------------------------------------------------------
extern "C" void kernel_launch(void* const* d_in, const int* in_sizes, int n_in,
                              void* d_out, int out_size)
{
    const float* feats      = (const float*)d_in[0];
    const float* W0         = (const float*)d_in[1];
    const float* b0         = (const float*)d_in[2];
    const float* W1         = (const float*)d_in[3];
    const float* b1         = (const float*)d_in[4];
    const int*   neigh_idx0 = (const int*)  d_in[5];
    const int*   neigh_idx1 = (const int*)  d_in[6];
    const int*   node_ids2  = (const int*)  d_in[8];
    float*       out        = (float*)d_out;

    __half* v2h;  cudaGetSymbolAddress((void**)&v2h,  g_v2h);
    __half* agg1; cudaGetSymbolAddress((void**)&agg1, g_agg1);
    __half* h1h;  cudaGetSymbolAddress((void**)&h1h,  g_h1h);
    __half* agg0; cudaGetSymbolAddress((void**)&agg0, g_agg0);

    {
        const int half_total = (N2V / 2) * (DD / 4);
        gather_v2h_kernel<<<(half_total + 255) / 256, 256>>>(feats, node_ids2);
    }
    // Hop-1: aggregate then GEMM.
    agg_mean_kernel<<<(N1V + 15) / 16, 256>>>(
        (const uint4*)v2h, neigh_idx1, agg1, N1V);
    gemm64_kernel<true ><<<(N1V + 127) / 128, 256>>>(
        agg1, W0, b0, (void*)h1h, N1V);
    // Seed: aggregate then GEMM (fp32 out).
    agg_mean_kernel<<<(N0V + 15) / 16, 256>>>(
        (const uint4*)h1h, neigh_idx0, agg0, N0V);
    gemm64_kernel<false><<<N0V / 128, 256>>>(
        agg0, W1, b1, (void*)out, N0V);
}

// round 13
// speedup vs baseline: 1.0049x; 1.0049x over previous
#include <cuda_runtime.h>
#include <cuda_fp16.h>

#define N0V   8192
#define N1V   100000
#define N2V   300000
#define KNBR  32
#define DD    64

typedef unsigned long long u64t;

#define PACKU64(out, lo, hi)  asm("mov.b64 %0, {%1, %2};" : "=l"(out) : "f"(lo), "f"(hi))
#define SPLATF64(out, v)      asm("mov.b64 %0, {%1, %1};" : "=l"(out) : "f"(v))
#define UNPACKF64(lo, hi, in) asm("mov.b64 {%0, %1}, %2;" : "=f"(lo), "=f"(hi) : "l"(in))
#define FFMA2(acc, a, b)      asm("fma.rn.f32x2 %0, %1, %2, %0;" : "+l"(acc) : "l"(a), "l"(b))

// Scratch (device globals — allocation in kernel_launch is forbidden).
__device__ __half g_v2h[(size_t)N2V * DD];    // 38.4 MB gather target
__device__ __half g_agg1[(size_t)N1V * DD];   // 12.8 MB hop-1 aggregates
__device__ __half g_h1h[(size_t)N1V * DD];    // 12.8 MB hop-1 activations
__device__ __half g_agg0[(size_t)N0V * DD];   // 1 MB   seed aggregates

// ---------------------------------------------------------------------------
// K1: v2h = half(feats[node_ids2]); 4 rows per thread (deep MLP vs DRAM lat).
// ---------------------------------------------------------------------------
__global__ void gather_v2h_kernel(const float* __restrict__ feats,
                                  const int*   __restrict__ node_ids2)
{
    int t = blockIdx.x * blockDim.x + threadIdx.x;
    const int Q = N2V / 4;                       // 75000
    const int quarter_total = Q * (DD / 4);
    if (t >= quarter_total) return;
    int row = t >> 4;
    int c   = t & 15;

    int  src[4];
    #pragma unroll
    for (int q = 0; q < 4; ++q)
        src[q] = __ldg(node_ids2 + row + q * Q);

    float4 v[4];
    #pragma unroll
    for (int q = 0; q < 4; ++q)
        v[q] = __ldg((const float4*)(feats + (size_t)src[q] * DD) + c);

    #pragma unroll
    for (int q = 0; q < 4; ++q) {
        __half2 h0 = __floats2half2_rn(v[q].x, v[q].y);
        __half2 h1 = __floats2half2_rn(v[q].z, v[q].w);
        uint2 p;
        p.x = *(unsigned int*)&h0;
        p.y = *(unsigned int*)&h1;
        ((uint2*)g_v2h)[(size_t)(row + q * Q) * 16 + c] = p;
    }
}

// ---------------------------------------------------------------------------
// Wide-load gather-mean, 2 rows/warp (validated — used for hop-1).
// ---------------------------------------------------------------------------
__global__ void __launch_bounds__(256) agg_mean_kernel(
    const uint4* __restrict__ vsrc,
    const int*   __restrict__ nbr,
    __half*      __restrict__ aggout,
    int nrows)
{
    const int tid  = threadIdx.x;
    const int lane = tid & 31;
    const int warp = tid >> 5;
    const int rowA = blockIdx.x * 16 + warp * 2;
    const int rowB = rowA + 1;
    const int crA = min(rowA, nrows - 1);
    const int crB = min(rowB, nrows - 1);

    const int idxA = __ldg(nbr + (size_t)crA * KNBR + lane);
    const int idxB = __ldg(nbr + (size_t)crB * KNBR + lane);

    const int sub = lane >> 3;
    const int ch  = lane & 7;

    __half2 zero = __float2half2_rn(0.f);
    __half2 aAcc[2][4], bAcc[2][4];
    #pragma unroll
    for (int s = 0; s < 2; ++s)
        #pragma unroll
        for (int j = 0; j < 4; ++j) { aAcc[s][j] = zero; bAcc[s][j] = zero; }

    #pragma unroll
    for (int i = 0; i < 8; ++i) {
        int nA = __shfl_sync(0xffffffffu, idxA, 4 * i + sub);
        int nB = __shfl_sync(0xffffffffu, idxB, 4 * i + sub);
        uint4 dA = __ldg(vsrc + (size_t)nA * 8 + ch);
        uint4 dB = __ldg(vsrc + (size_t)nB * 8 + ch);
        const __half2* hA = (const __half2*)&dA;
        const __half2* hB = (const __half2*)&dB;
        int s = i & 1;
        #pragma unroll
        for (int j = 0; j < 4; ++j) {
            aAcc[s][j] = __hadd2(aAcc[s][j], hA[j]);
            bAcc[s][j] = __hadd2(bAcc[s][j], hB[j]);
        }
    }

    float fA[8], fB[8];
    #pragma unroll
    for (int j = 0; j < 4; ++j) {
        float2 va = __half22float2(__hadd2(aAcc[0][j], aAcc[1][j]));
        float2 vb = __half22float2(__hadd2(bAcc[0][j], bAcc[1][j]));
        fA[2 * j] = va.x;  fA[2 * j + 1] = va.y;
        fB[2 * j] = vb.x;  fB[2 * j + 1] = vb.y;
    }

    #pragma unroll
    for (int d = 8; d <= 16; d <<= 1) {
        #pragma unroll
        for (int j = 0; j < 8; ++j) {
            fA[j] += __shfl_xor_sync(0xffffffffu, fA[j], d);
            fB[j] += __shfl_xor_sync(0xffffffffu, fB[j], d);
        }
    }

    const float inv = 1.0f / KNBR;
    if (sub == 0 && rowA < nrows) {
        __half2 h[4];
        #pragma unroll
        for (int j = 0; j < 4; ++j)
            h[j] = __floats2half2_rn(fA[2 * j] * inv, fA[2 * j + 1] * inv);
        ((uint4*)aggout)[(size_t)rowA * 8 + ch] = *(uint4*)h;
    }
    if (sub == 1 && rowB < nrows) {
        __half2 h[4];
        #pragma unroll
        for (int j = 0; j < 4; ++j)
            h[j] = __floats2half2_rn(fB[2 * j] * inv, fB[2 * j + 1] * inv);
        ((uint4*)aggout)[(size_t)rowB * 8 + ch] = *(uint4*)h;
    }
}

// ---------------------------------------------------------------------------
// Seed aggregation: 1 row/warp (more parallelism for the short seed layer).
// grid = nrows/8 blocks of 256.
// ---------------------------------------------------------------------------
__global__ void __launch_bounds__(256) agg_mean1_kernel(
    const uint4* __restrict__ vsrc,
    const int*   __restrict__ nbr,
    __half*      __restrict__ aggout,
    int nrows)
{
    const int tid  = threadIdx.x;
    const int lane = tid & 31;
    const int warp = tid >> 5;
    const int row  = blockIdx.x * 8 + warp;
    if (row >= nrows) return;

    const int idx = __ldg(nbr + (size_t)row * KNBR + lane);
    const int sub = lane >> 3;
    const int ch  = lane & 7;

    __half2 zero = __float2half2_rn(0.f);
    __half2 acc[2][4];
    #pragma unroll
    for (int s = 0; s < 2; ++s)
        #pragma unroll
        for (int j = 0; j < 4; ++j) acc[s][j] = zero;

    #pragma unroll
    for (int i = 0; i < 8; ++i) {
        int n = __shfl_sync(0xffffffffu, idx, 4 * i + sub);
        uint4 d = __ldg(vsrc + (size_t)n * 8 + ch);
        const __half2* h = (const __half2*)&d;
        int s = i & 1;
        #pragma unroll
        for (int j = 0; j < 4; ++j)
            acc[s][j] = __hadd2(acc[s][j], h[j]);
    }

    float f[8];
    #pragma unroll
    for (int j = 0; j < 4; ++j) {
        float2 v = __half22float2(__hadd2(acc[0][j], acc[1][j]));
        f[2 * j] = v.x;  f[2 * j + 1] = v.y;
    }
    #pragma unroll
    for (int d = 8; d <= 16; d <<= 1)
        #pragma unroll
        for (int j = 0; j < 8; ++j)
            f[j] += __shfl_xor_sync(0xffffffffu, f[j], d);

    const float inv = 1.0f / KNBR;
    if (sub == 0) {
        __half2 h[4];
        #pragma unroll
        for (int j = 0; j < 4; ++j)
            h[j] = __floats2half2_rn(f[2 * j] * inv, f[2 * j + 1] * inv);
        ((uint4*)aggout)[(size_t)row * 8 + ch] = *(uint4*)h;
    }
}

// ---------------------------------------------------------------------------
// FFMA GEMM: out = relu(A @ W + b), A fp16 [nrows,64].
// sA stride 68 halfs: the 4 distinct row-addresses per A-load land 8 banks
// apart -> conflict-free LDS (was 2-way at stride 72). Staged via uint2.
// ---------------------------------------------------------------------------
#define SA_STRIDE 68

template<bool HALF_OUT>
__global__ void __launch_bounds__(256) gemm64_kernel(
    const __half* __restrict__ A,
    const float*  __restrict__ W,
    const float*  __restrict__ bias,
    void*         __restrict__ out,
    int nrows)
{
    __shared__ float  sW[DD * DD];
    __shared__ __half sA[128 * SA_STRIDE];

    const int tid = threadIdx.x;
    #pragma unroll
    for (int i = tid; i < DD * DD / 4; i += 256)
        ((float4*)sW)[i] = __ldg((const float4*)W + i);

    const int rowbase = blockIdx.x * 128;
    // Stage A: 128 rows x 64 halfs = 2048 uint2 (8B each).
    for (int i = tid; i < 2048; i += 256) {
        int r = i >> 4, c = i & 15;
        int gr = min(rowbase + r, nrows - 1);
        uint2 v = __ldg((const uint2*)(A + (size_t)gr * DD) + c);
        *(uint2*)&sA[r * SA_STRIDE + c * 4] = v;
    }
    __syncthreads();

    const int rp   = tid >> 3;
    const int col0 = (tid & 7) * 8;

    float4 bv0 = __ldg((const float4*)(bias + col0));
    float4 bv1 = __ldg((const float4*)(bias + col0 + 4));
    u64t bp[4];
    PACKU64(bp[0], bv0.x, bv0.y);  PACKU64(bp[1], bv0.z, bv0.w);
    PACKU64(bp[2], bv1.x, bv1.y);  PACKU64(bp[3], bv1.z, bv1.w);
    u64t acc[4][4];
    #pragma unroll
    for (int r = 0; r < 4; ++r)
        #pragma unroll
        for (int j = 0; j < 4; ++j) acc[r][j] = bp[j];

    #pragma unroll
    for (int k = 0; k < DD; k += 2) {
        ulonglong2 wA01 = *(const ulonglong2*)&sW[k * DD + col0];
        ulonglong2 wA23 = *(const ulonglong2*)&sW[k * DD + col0 + 4];
        ulonglong2 wB01 = *(const ulonglong2*)&sW[(k + 1) * DD + col0];
        ulonglong2 wB23 = *(const ulonglong2*)&sW[(k + 1) * DD + col0 + 4];
        #pragma unroll
        for (int r = 0; r < 4; ++r) {
            __half2 ah = *(const __half2*)&sA[(4 * rp + r) * SA_STRIDE + k];
            float2 af = __half22float2(ah);
            u64t s0, s1;
            SPLATF64(s0, af.x);
            SPLATF64(s1, af.y);
            FFMA2(acc[r][0], s0, wA01.x);  FFMA2(acc[r][1], s0, wA01.y);
            FFMA2(acc[r][2], s0, wA23.x);  FFMA2(acc[r][3], s0, wA23.y);
            FFMA2(acc[r][0], s1, wB01.x);  FFMA2(acc[r][1], s1, wB01.y);
            FFMA2(acc[r][2], s1, wB23.x);  FFMA2(acc[r][3], s1, wB23.y);
        }
    }

    #pragma unroll
    for (int r = 0; r < 4; ++r) {
        int grow = rowbase + 4 * rp + r;
        if (grow >= nrows) continue;
        if (HALF_OUT) {
            __half2 h[4];
            #pragma unroll
            for (int j = 0; j < 4; ++j) {
                float lo, hi;
                UNPACKF64(lo, hi, acc[r][j]);
                h[j] = __floats2half2_rn(fmaxf(lo, 0.f), fmaxf(hi, 0.f));
            }
            *(uint4*)((__half*)out + (size_t)grow * DD + col0) = *(uint4*)h;
        } else {
            float* op = (float*)out + (size_t)grow * DD + col0;
            #pragma unroll
            for (int j = 0; j < 4; ++j) {
                float lo, hi;
                UNPACKF64(lo, hi, acc[r][j]);
                op[2 * j]     = fmaxf(lo, 0.f);
                op[2 * j + 1] = fmaxf(hi, 0.f);
            }
        }
    }
}

// ---------------------------------------------------------------------------
// Inputs: 0 feats, 1 W0, 2 b0, 3 W1, 4 b1, 5 neigh_idx0, 6 neigh_idx1,
//         7 node_ids1 (unused), 8 node_ids2
// ---------------------------------------------------------------------------
extern "C" void kernel_launch(void* const* d_in, const int* in_sizes, int n_in,
                              void* d_out, int out_size)
{
    const float* feats      = (const float*)d_in[0];
    const float* W0         = (const float*)d_in[1];
    const float* b0         = (const float*)d_in[2];
    const float* W1         = (const float*)d_in[3];
    const float* b1         = (const float*)d_in[4];
    const int*   neigh_idx0 = (const int*)  d_in[5];
    const int*   neigh_idx1 = (const int*)  d_in[6];
    const int*   node_ids2  = (const int*)  d_in[8];
    float*       out        = (float*)d_out;

    __half* v2h;  cudaGetSymbolAddress((void**)&v2h,  g_v2h);
    __half* agg1; cudaGetSymbolAddress((void**)&agg1, g_agg1);
    __half* h1h;  cudaGetSymbolAddress((void**)&h1h,  g_h1h);
    __half* agg0; cudaGetSymbolAddress((void**)&agg0, g_agg0);

    {
        const int quarter_total = (N2V / 4) * (DD / 4);
        gather_v2h_kernel<<<(quarter_total + 255) / 256, 256>>>(feats, node_ids2);
    }
    // Hop-1: aggregate then GEMM.
    agg_mean_kernel<<<(N1V + 15) / 16, 256>>>(
        (const uint4*)v2h, neigh_idx1, agg1, N1V);
    gemm64_kernel<true ><<<(N1V + 127) / 128, 256>>>(
        agg1, W0, b0, (void*)h1h, N1V);
    // Seed: aggregate (1 row/warp) then GEMM (fp32 out).
    agg_mean1_kernel<<<N0V / 8, 256>>>(
        (const uint4*)h1h, neigh_idx0, agg0, N0V);
    gemm64_kernel<false><<<N0V / 128, 256>>>(
        agg0, W1, b1, (void*)out, N0V);
}

// round 14
// speedup vs baseline: 1.0663x; 1.0611x over previous
#include <cuda_runtime.h>
#include <cuda_fp16.h>

#define N0V   8192
#define N1V   100000
#define N2V   300000
#define KNBR  32
#define DD    64

typedef unsigned long long u64t;

#define PACKU64(out, lo, hi)  asm("mov.b64 %0, {%1, %2};" : "=l"(out) : "f"(lo), "f"(hi))
#define SPLATF64(out, v)      asm("mov.b64 %0, {%1, %1};" : "=l"(out) : "f"(v))
#define UNPACKF64(lo, hi, in) asm("mov.b64 {%0, %1}, %2;" : "=f"(lo), "=f"(hi) : "l"(in))
#define FFMA2(acc, a, b)      asm("fma.rn.f32x2 %0, %1, %2, %0;" : "+l"(acc) : "l"(a), "l"(b))

// Scratch (device globals — allocation in kernel_launch is forbidden).
__device__ __half g_v2h[(size_t)N2V * DD];    // 38.4 MB gather target
__device__ __half g_agg1[(size_t)N1V * DD];   // 12.8 MB hop-1 aggregates
__device__ __half g_h1h[(size_t)N1V * DD];    // 12.8 MB hop-1 activations
__device__ __half g_agg0[(size_t)N0V * DD];   // 1 MB   seed aggregates

// ---------------------------------------------------------------------------
// K1: v2h = half(feats[node_ids2]); 4 rows per thread. First kernel: no sync.
// ---------------------------------------------------------------------------
__global__ void gather_v2h_kernel(const float* __restrict__ feats,
                                  const int*   __restrict__ node_ids2)
{
    int t = blockIdx.x * blockDim.x + threadIdx.x;
    const int Q = N2V / 4;
    const int quarter_total = Q * (DD / 4);
    if (t >= quarter_total) return;
    int row = t >> 4;
    int c   = t & 15;

    int src[4];
    #pragma unroll
    for (int q = 0; q < 4; ++q)
        src[q] = __ldg(node_ids2 + row + q * Q);

    float4 v[4];
    #pragma unroll
    for (int q = 0; q < 4; ++q)
        v[q] = __ldg((const float4*)(feats + (size_t)src[q] * DD) + c);

    #pragma unroll
    for (int q = 0; q < 4; ++q) {
        __half2 h0 = __floats2half2_rn(v[q].x, v[q].y);
        __half2 h1 = __floats2half2_rn(v[q].z, v[q].w);
        uint2 p;
        p.x = *(unsigned int*)&h0;
        p.y = *(unsigned int*)&h1;
        ((uint2*)g_v2h)[(size_t)(row + q * Q) * 16 + c] = p;
    }
}

// ---------------------------------------------------------------------------
// Gather-mean, 1 row/warp (best-profiling structure: occ 78%, issue 28%).
// PDL: loads neighbor indices (independent input) BEFORE the grid-dependency
// sync; gathers from vsrc (predecessor output) after.
// ---------------------------------------------------------------------------
__global__ void __launch_bounds__(256) agg_mean1_kernel(
    const uint4* __restrict__ vsrc,
    const int*   __restrict__ nbr,
    __half*      __restrict__ aggout,
    int nrows)
{
    const int tid  = threadIdx.x;
    const int lane = tid & 31;
    const int warp = tid >> 5;
    const int row  = blockIdx.x * 8 + warp;
    const int cr   = min(row, nrows - 1);

    // Prelude: index load is independent of the predecessor kernel.
    const int idx = __ldg(nbr + (size_t)cr * KNBR + lane);

    cudaGridDependencySynchronize();   // wait for predecessor writes to vsrc

    if (row >= nrows) return;
    const int sub = lane >> 3;
    const int ch  = lane & 7;

    __half2 zero = __float2half2_rn(0.f);
    __half2 acc[2][4];
    #pragma unroll
    for (int s = 0; s < 2; ++s)
        #pragma unroll
        for (int j = 0; j < 4; ++j) acc[s][j] = zero;

    #pragma unroll
    for (int i = 0; i < 8; ++i) {
        int n = __shfl_sync(0xffffffffu, idx, 4 * i + sub);
        uint4 d = __ldg(vsrc + (size_t)n * 8 + ch);
        const __half2* h = (const __half2*)&d;
        int s = i & 1;
        #pragma unroll
        for (int j = 0; j < 4; ++j)
            acc[s][j] = __hadd2(acc[s][j], h[j]);
    }

    float f[8];
    #pragma unroll
    for (int j = 0; j < 4; ++j) {
        float2 v = __half22float2(__hadd2(acc[0][j], acc[1][j]));
        f[2 * j] = v.x;  f[2 * j + 1] = v.y;
    }
    #pragma unroll
    for (int d = 8; d <= 16; d <<= 1)
        #pragma unroll
        for (int j = 0; j < 8; ++j)
            f[j] += __shfl_xor_sync(0xffffffffu, f[j], d);

    const float inv = 1.0f / KNBR;
    if (sub == 0) {
        __half2 h[4];
        #pragma unroll
        for (int j = 0; j < 4; ++j)
            h[j] = __floats2half2_rn(f[2 * j] * inv, f[2 * j + 1] * inv);
        ((uint4*)aggout)[(size_t)row * 8 + ch] = *(uint4*)h;
    }
}

// ---------------------------------------------------------------------------
// FFMA GEMM: out = relu(A @ W + b), A fp16 [nrows,64].
// PDL: stages W and bias (independent inputs) before the sync; A after.
// ---------------------------------------------------------------------------
#define SA_STRIDE 68

template<bool HALF_OUT>
__global__ void __launch_bounds__(256) gemm64_kernel(
    const __half* __restrict__ A,
    const float*  __restrict__ W,
    const float*  __restrict__ bias,
    void*         __restrict__ out,
    int nrows)
{
    __shared__ float  sW[DD * DD];
    __shared__ __half sA[128 * SA_STRIDE];

    const int tid = threadIdx.x;

    // Prelude: W + bias are kernel inputs, independent of predecessor.
    #pragma unroll
    for (int i = tid; i < DD * DD / 4; i += 256)
        ((float4*)sW)[i] = __ldg((const float4*)W + i);

    const int rp   = tid >> 3;
    const int col0 = (tid & 7) * 8;
    float4 bv0 = __ldg((const float4*)(bias + col0));
    float4 bv1 = __ldg((const float4*)(bias + col0 + 4));

    cudaGridDependencySynchronize();   // wait for predecessor writes to A

    const int rowbase = blockIdx.x * 128;
    for (int i = tid; i < 2048; i += 256) {
        int r = i >> 4, c = i & 15;
        int gr = min(rowbase + r, nrows - 1);
        uint2 v = __ldg((const uint2*)(A + (size_t)gr * DD) + c);
        *(uint2*)&sA[r * SA_STRIDE + c * 4] = v;
    }
    __syncthreads();

    u64t bp[4];
    PACKU64(bp[0], bv0.x, bv0.y);  PACKU64(bp[1], bv0.z, bv0.w);
    PACKU64(bp[2], bv1.x, bv1.y);  PACKU64(bp[3], bv1.z, bv1.w);
    u64t acc[4][4];
    #pragma unroll
    for (int r = 0; r < 4; ++r)
        #pragma unroll
        for (int j = 0; j < 4; ++j) acc[r][j] = bp[j];

    #pragma unroll
    for (int k = 0; k < DD; k += 2) {
        ulonglong2 wA01 = *(const ulonglong2*)&sW[k * DD + col0];
        ulonglong2 wA23 = *(const ulonglong2*)&sW[k * DD + col0 + 4];
        ulonglong2 wB01 = *(const ulonglong2*)&sW[(k + 1) * DD + col0];
        ulonglong2 wB23 = *(const ulonglong2*)&sW[(k + 1) * DD + col0 + 4];
        #pragma unroll
        for (int r = 0; r < 4; ++r) {
            __half2 ah = *(const __half2*)&sA[(4 * rp + r) * SA_STRIDE + k];
            float2 af = __half22float2(ah);
            u64t s0, s1;
            SPLATF64(s0, af.x);
            SPLATF64(s1, af.y);
            FFMA2(acc[r][0], s0, wA01.x);  FFMA2(acc[r][1], s0, wA01.y);
            FFMA2(acc[r][2], s0, wA23.x);  FFMA2(acc[r][3], s0, wA23.y);
            FFMA2(acc[r][0], s1, wB01.x);  FFMA2(acc[r][1], s1, wB01.y);
            FFMA2(acc[r][2], s1, wB23.x);  FFMA2(acc[r][3], s1, wB23.y);
        }
    }

    #pragma unroll
    for (int r = 0; r < 4; ++r) {
        int grow = rowbase + 4 * rp + r;
        if (grow >= nrows) continue;
        if (HALF_OUT) {
            __half2 h[4];
            #pragma unroll
            for (int j = 0; j < 4; ++j) {
                float lo, hi;
                UNPACKF64(lo, hi, acc[r][j]);
                h[j] = __floats2half2_rn(fmaxf(lo, 0.f), fmaxf(hi, 0.f));
            }
            *(uint4*)((__half*)out + (size_t)grow * DD + col0) = *(uint4*)h;
        } else {
            float* op = (float*)out + (size_t)grow * DD + col0;
            #pragma unroll
            for (int j = 0; j < 4; ++j) {
                float lo, hi;
                UNPACKF64(lo, hi, acc[r][j]);
                op[2 * j]     = fmaxf(lo, 0.f);
                op[2 * j + 1] = fmaxf(hi, 0.f);
            }
        }
    }
}

// ---------------------------------------------------------------------------
// Launch: 5-kernel chain with PDL edges (secondaries launch early, run their
// independent-input preludes, then grid-dependency-sync before consuming).
// Inputs: 0 feats, 1 W0, 2 b0, 3 W1, 4 b1, 5 neigh_idx0, 6 neigh_idx1,
//         7 node_ids1 (unused), 8 node_ids2
// ---------------------------------------------------------------------------
template<typename... Args>
static void launch_pdl(void (*kern)(Args...), dim3 grid, dim3 block, Args... args)
{
    cudaLaunchConfig_t cfg = {};
    cfg.gridDim  = grid;
    cfg.blockDim = block;
    cfg.stream   = 0;
    cudaLaunchAttribute attr[1];
    attr[0].id = cudaLaunchAttributeProgrammaticStreamSerialization;
    attr[0].val.programmaticStreamSerializationAllowed = 1;
    cfg.attrs = attr;
    cfg.numAttrs = 1;
    cudaLaunchKernelEx(&cfg, kern, args...);
}

extern "C" void kernel_launch(void* const* d_in, const int* in_sizes, int n_in,
                              void* d_out, int out_size)
{
    const float* feats      = (const float*)d_in[0];
    const float* W0         = (const float*)d_in[1];
    const float* b0         = (const float*)d_in[2];
    const float* W1         = (const float*)d_in[3];
    const float* b1         = (const float*)d_in[4];
    const int*   neigh_idx0 = (const int*)  d_in[5];
    const int*   neigh_idx1 = (const int*)  d_in[6];
    const int*   node_ids2  = (const int*)  d_in[8];
    float*       out        = (float*)d_out;

    __half* v2h;  cudaGetSymbolAddress((void**)&v2h,  g_v2h);
    __half* agg1; cudaGetSymbolAddress((void**)&agg1, g_agg1);
    __half* h1h;  cudaGetSymbolAddress((void**)&h1h,  g_h1h);
    __half* agg0; cudaGetSymbolAddress((void**)&agg0, g_agg0);

    // K1 (no predecessor): plain launch.
    {
        const int quarter_total = (N2V / 4) * (DD / 4);
        gather_v2h_kernel<<<(quarter_total + 255) / 256, 256>>>(feats, node_ids2);
    }
    // K2: hop-1 aggregation (1 row/warp), PDL on K1.
    launch_pdl(agg_mean1_kernel, dim3((N1V + 7) / 8), dim3(256),
               (const uint4*)v2h, neigh_idx1, agg1, N1V);
    // K3: hop-1 GEMM, PDL on K2.
    launch_pdl(gemm64_kernel<true>, dim3((N1V + 127) / 128), dim3(256),
               (const __half*)agg1, W0, b0, (void*)h1h, N1V);
    // K4: seed aggregation, PDL on K3.
    launch_pdl(agg_mean1_kernel, dim3(N0V / 8), dim3(256),
               (const uint4*)h1h, neigh_idx0, agg0, N0V);
    // K5: seed GEMM (fp32 out), PDL on K4.
    launch_pdl(gemm64_kernel<false>, dim3(N0V / 128), dim3(256),
               (const __half*)agg0, W1, b1, (void*)out, N0V);
}